// round 7
// baseline (speedup 1.0000x reference)
#include <cuda_runtime.h>
#include <math.h>

typedef unsigned long long u64;
typedef unsigned int u32;

#define FSZ 50
#define NPOS 2500          // 50*50
#define KTOT 4608          // 512*9
#define NPAD 2560          // padded N for GEMM
#define NANCH 22500        // 2500*9
#define PRE_NMS 6000
#define NWORDS 94          // ceil(6000/64)
#define POST_NMS 300
#define NBINS 65536
#define CAND_N 8192

// GEMM config
#define TM 128
#define TN 128
#define TK 16
#define SPLITK 4
#define KS (KTOT / SPLITK)       // 1152
#define GITERS (KS / TK)         // 72
#define ASTR 132                 // padded smem row stride (floats)

// ---------------- scratch (__device__ globals; no runtime allocation) ----------------
__device__ float g_im2col[(size_t)KTOT * NPAD];          // 47.2 MB, [k][n]
__device__ float g_part[SPLITK][512][NPAD];              // 21 MB split-K partials
__device__ float g_feat[(size_t)512 * NPAD];             // 5.2 MB, [m][n] channel-major
__device__ float g_head[(size_t)64 * NPAD];              // 0.66 MB
__device__ float g_boxes[NANCH * 4];
__device__ u64   g_keys[NANCH];
__device__ int   g_hist[NBINS];
__device__ int   g_cnt;
__device__ int   g_cut;
__device__ u64   g_cand[CAND_N];
__device__ float g_sx1[PRE_NMS], g_sy1[PRE_NMS], g_sx2[PRE_NMS], g_sy2[PRE_NMS], g_sarea[PRE_NMS];
__device__ u64   g_maskT[(size_t)NWORDS * PRE_NMS + 64]; // transposed [word][box] + OOB pad

// ---------------- packed fp32 helpers ----------------
__device__ __forceinline__ u64 bcast2(float x) {
    u64 r; asm("mov.b64 %0, {%1, %1};" : "=l"(r) : "f"(x)); return r;
}
__device__ __forceinline__ void ffma2(u64& acc, u64 a, u64 b) {
    asm("fma.rn.f32x2 %0, %1, %2, %0;" : "+l"(acc) : "l"(a), "l"(b));
}
__device__ __forceinline__ void unpack2(u64 v, float& lo, float& hi) {
    asm("mov.b64 {%0, %1}, %2;" : "=f"(lo), "=f"(hi) : "l"(v));
}
#define CPA(dst, src)  asm volatile("cp.async.cg.shared.global [%0], [%1], 16;" :: "r"(dst), "l"(src))
#define CPCOMMIT()     asm volatile("cp.async.commit_group;" ::: "memory")
#define CPWAIT0()      asm volatile("cp.async.wait_group 0;" ::: "memory")

// ---------------- im2col (batch 7 only) ----------------
__global__ void im2col_k(const float* __restrict__ x) {
    size_t idx = (size_t)blockIdx.x * 256 + threadIdx.x;
    if (idx >= (size_t)KTOT * NPAD) return;
    int k = (int)(idx / NPAD);
    int p = (int)(idx - (size_t)k * NPAD);
    float v = 0.f;
    if (p < NPOS) {
        int i  = k / 9;
        int r  = k - i * 9;
        int ky = r / 3;
        int kx = r - ky * 3;
        int y  = p / FSZ;
        int xw = p - y * FSZ;
        int yy = y + ky - 1;
        int xx = xw + kx - 1;
        if (yy >= 0 && yy < FSZ && xx >= 0 && xx < FSZ)
            v = x[(size_t)i * NPOS + yy * FSZ + xx];
    }
    g_im2col[idx] = v;
}

// ---------------- packed-fp32 split-K GEMM (conflict-free compute mapping) ----------------
__global__ __launch_bounds__(256) void conv_gemm_k(const float* __restrict__ W) {
    __shared__ __align__(16) float As[2][TK][ASTR];   // [k][m]
    __shared__ __align__(16) float Bs[2][TK][ASTR];   // [k][n]
    int t  = threadIdx.x;
    int m0 = blockIdx.y * TM;
    int n0 = blockIdx.x * TN;
    int z  = blockIdx.z;
    int kbase = z * KS;

    int arow = t >> 1;
    int ak   = (t & 1) * 8;
    int brow = t >> 4;
    int bn   = (t & 15) * 4;

    const float* aG = W + (size_t)(m0 + arow) * KTOT + kbase + ak;
    const float* bG = g_im2col + (size_t)(kbase + brow) * NPAD + n0 + bn;

    u32 bs0 = (u32)__cvta_generic_to_shared(&Bs[0][0][0]) + (u32)((brow * ASTR + bn) * 4);
    u32 bs1 = bs0 + (u32)(TK * ASTR * 4);

    float4 ar0 = *(const float4*)aG;
    float4 ar1 = *(const float4*)(aG + 4);
    CPA(bs0, bG);
    CPA(bs0 + 256, bG + 64);
    CPCOMMIT();

    u64 acc[4][8];
#pragma unroll
    for (int i = 0; i < 4; ++i)
#pragma unroll
        for (int j = 0; j < 8; ++j) acc[i][j] = 0ull;

    int warp = t >> 5, lane = t & 31;
    int mwarp = warp >> 1, nwarp = warp & 1;
    int lm = lane >> 3, ln = lane & 7;
    int mb = mwarp * 32 + lm * 4;
    int nb = nwarp * 64 + ln * 4;

    for (int it = 0; it < GITERS; ++it) {
        int cur = it & 1;
        CPWAIT0();
        {
            float* Ac = &As[cur][0][0];
            Ac[(ak + 0) * ASTR + arow] = ar0.x;
            Ac[(ak + 1) * ASTR + arow] = ar0.y;
            Ac[(ak + 2) * ASTR + arow] = ar0.z;
            Ac[(ak + 3) * ASTR + arow] = ar0.w;
            Ac[(ak + 4) * ASTR + arow] = ar1.x;
            Ac[(ak + 5) * ASTR + arow] = ar1.y;
            Ac[(ak + 6) * ASTR + arow] = ar1.z;
            Ac[(ak + 7) * ASTR + arow] = ar1.w;
        }
        __syncthreads();

        if (it + 1 < GITERS) {
            int nxt = cur ^ 1;
            const float* bGn = bG + (size_t)(it + 1) * TK * NPAD;
            u32 bsn = nxt ? bs1 : bs0;
            CPA(bsn, bGn);
            CPA(bsn + 256, bGn + 64);
            CPCOMMIT();
            const float* aGn = aG + (it + 1) * TK;
            ar0 = *(const float4*)aGn;
            ar1 = *(const float4*)(aGn + 4);
        }

#pragma unroll
        for (int kk = 0; kk < TK; ++kk) {
            const float* asr = &As[cur][kk][0];
            const float* bsr = &Bs[cur][kk][0];
            ulonglong2 a0 = *(const ulonglong2*)(asr + mb);
            ulonglong2 a1 = *(const ulonglong2*)(asr + mb + 16);
            float4 b0 = *(const float4*)(bsr + nb);
            float4 b1 = *(const float4*)(bsr + nb + 32);
            u64 aa[4] = {a0.x, a0.y, a1.x, a1.y};
            u64 bb[8];
            bb[0] = bcast2(b0.x); bb[1] = bcast2(b0.y);
            bb[2] = bcast2(b0.z); bb[3] = bcast2(b0.w);
            bb[4] = bcast2(b1.x); bb[5] = bcast2(b1.y);
            bb[6] = bcast2(b1.z); bb[7] = bcast2(b1.w);
#pragma unroll
            for (int mp = 0; mp < 4; ++mp)
#pragma unroll
                for (int nj = 0; nj < 8; ++nj)
                    ffma2(acc[mp][nj], aa[mp], bb[nj]);
        }
        __syncthreads();
    }

    float* outp = &g_part[z][0][0];
#pragma unroll
    for (int mp = 0; mp < 4; ++mp) {
        float lo[8], hi[8];
#pragma unroll
        for (int nj = 0; nj < 8; ++nj) unpack2(acc[mp][nj], lo[nj], hi[nj]);
        int m = m0 + mb + ((mp & 2) << 3) + ((mp & 1) << 1);
        size_t rA = (size_t)m * NPAD + n0 + nb;
        size_t rB = rA + NPAD;
        float4 v;
        v.x = lo[0]; v.y = lo[1]; v.z = lo[2]; v.w = lo[3]; *(float4*)(outp + rA)      = v;
        v.x = lo[4]; v.y = lo[5]; v.z = lo[6]; v.w = lo[7]; *(float4*)(outp + rA + 32) = v;
        v.x = hi[0]; v.y = hi[1]; v.z = hi[2]; v.w = hi[3]; *(float4*)(outp + rB)      = v;
        v.x = hi[4]; v.y = hi[5]; v.z = hi[6]; v.w = hi[7]; *(float4*)(outp + rB + 32) = v;
    }
}

// ---------------- reduce splits + bias + leaky -> g_feat[m][n] ----------------
__global__ void reduce_bias_k(const float* __restrict__ bias) {
    int idx = blockIdx.x * 256 + threadIdx.x;
    const int N4 = NPAD / 4;
    if (idx >= 512 * N4) return;
    int m  = idx / N4;
    int n4 = idx - m * N4;
    size_t off = (size_t)m * NPAD + n4 * 4;
    float4 a = *(const float4*)(&g_part[0][0][0] + off);
    float4 b = *(const float4*)(&g_part[1][0][0] + off);
    float4 c = *(const float4*)(&g_part[2][0][0] + off);
    float4 d = *(const float4*)(&g_part[3][0][0] + off);
    float bv = bias[m];
    float4 o;
    float v;
    v = a.x + b.x + c.x + d.x + bv; o.x = (v >= 0.f) ? v : 0.01f * v;
    v = a.y + b.y + c.y + d.y + bv; o.y = (v >= 0.f) ? v : 0.01f * v;
    v = a.z + b.z + c.z + d.z + bv; o.z = (v >= 0.f) ? v : 0.01f * v;
    v = a.w + b.w + c.w + d.w + bv; o.w = (v >= 0.f) ? v : 0.01f * v;
    *(float4*)(g_feat + off) = o;
}

// ---------------- head GEMM: g_head[64][2560] = Whead[64][512] @ g_feat, 32-wide n tiles ----------------
__global__ __launch_bounds__(256) void head_gemm_k(const float* __restrict__ reg_w,
                                                   const float* __restrict__ reg_b,
                                                   const float* __restrict__ cls_w,
                                                   const float* __restrict__ cls_b) {
    __shared__ __align__(16) float As[16][68];   // [k][m] 64 m
    __shared__ __align__(16) float Bs[16][36];   // [k][n] 32 n
    int t  = threadIdx.x;
    int n0 = blockIdx.x * 32;

    int arow_h = t >> 2, akk = (t & 3) * 4;   // A: 64 rows x 16 k
    int brow = t >> 3, bnl = (t & 7) * 4;     // B: 16 k x 32 n (threads < 128)

    int warp = t >> 5, lane = t & 31;
    int mwarp = warp >> 1, nwarp = warp & 1;
    int lm = lane >> 3, ln = lane & 7;
    int mb = mwarp * 16 + lm * 4;
    int nb = nwarp * 16 + ln * 2;

    float acc[4][2];
#pragma unroll
    for (int i = 0; i < 4; ++i) { acc[i][0] = 0.f; acc[i][1] = 0.f; }

    for (int it = 0; it < 32; ++it) {
        int k0 = it * 16;
        float4 av;
        if (arow_h < 36)       av = *(const float4*)(reg_w + arow_h * 512 + k0 + akk);
        else if (arow_h < 54)  av = *(const float4*)(cls_w + (arow_h - 36) * 512 + k0 + akk);
        else                   av = make_float4(0.f, 0.f, 0.f, 0.f);
        float4 bv = make_float4(0.f, 0.f, 0.f, 0.f);
        if (t < 128) bv = *(const float4*)(g_feat + (size_t)(k0 + brow) * NPAD + n0 + bnl);
        __syncthreads();
        As[akk + 0][arow_h] = av.x;
        As[akk + 1][arow_h] = av.y;
        As[akk + 2][arow_h] = av.z;
        As[akk + 3][arow_h] = av.w;
        if (t < 128) *(float4*)&Bs[brow][bnl] = bv;
        __syncthreads();
#pragma unroll
        for (int kk = 0; kk < 16; ++kk) {
            float4 a4 = *(const float4*)(&As[kk][mb]);
            float2 b2 = *(const float2*)(&Bs[kk][nb]);
            float am[4] = {a4.x, a4.y, a4.z, a4.w};
#pragma unroll
            for (int mi = 0; mi < 4; ++mi) {
                acc[mi][0] = fmaf(am[mi], b2.x, acc[mi][0]);
                acc[mi][1] = fmaf(am[mi], b2.y, acc[mi][1]);
            }
        }
    }

#pragma unroll
    for (int mi = 0; mi < 4; ++mi) {
        int m = mb + mi;
        float bv = 0.f;
        if (m < 36) bv = reg_b[m];
        else if (m < 54) bv = cls_b[m - 36];
        float2 o;
        o.x = acc[mi][0] + bv;
        o.y = acc[mi][1] + bv;
        *(float2*)(g_head + (size_t)m * NPAD + n0 + nb) = o;
    }
}

// ---------------- decode: softmax + box decode + sort keys ----------------
__global__ void decode_k() {
    int p = blockIdx.x * 256 + threadIdx.x;
    if (p >= NPOS) return;
    float ho[54];
#pragma unroll
    for (int j = 0; j < 54; ++j) ho[j] = g_head[(size_t)j * NPAD + p];

    int irow = p / FSZ, jcol = p - irow * FSZ;
    float cx = 16.f * (float)irow + 8.f;
    float cy = 16.f * (float)jcol + 8.f;

#pragma unroll
    for (int a = 0; a < 9; ++a) {
        int r = a / 3, s = a % 3;
        float ssv = 16.0f * ((s == 0) ? 8.f : (s == 1) ? 16.f : 32.f);
        float rsv = (r == 0) ? 0.5f : (r == 1) ? 1.f : 2.f;
        float ha = ssv * sqrtf(rsv);
        float wa = ssv * sqrtf(1.0f / rsv);
        float x1a = cx - wa * 0.5f;
        float y1a = cy - ha * 0.5f;

        float pr0 = ho[a * 4 + 0], pr1 = ho[a * 4 + 1], pr2 = ho[a * 4 + 2], pr3 = ho[a * 4 + 3];
        float c0 = ho[36 + a * 2 + 0], c1 = ho[36 + a * 2 + 1];
        float mx = fmaxf(c0, c1);
        float e0 = expf(c0 - mx), e1 = expf(c1 - mx);
        float sc = e1 / (e0 + e1);

        const float hi = 799.f;
        float t0 = pr0 + x1a, t1 = pr1 + y1a;
        float rx1 = fminf(fmaxf(t0, 0.f), hi);
        float ry1 = fminf(fmaxf(t1, 0.f), hi);
        float rx2 = fminf(fmaxf((t0 + pr2) + wa, 0.f), hi);
        float ry2 = fminf(fmaxf((t1 + pr3) + ha, 0.f), hi);
        float wv = pr2 + wa, hv = pr3 + ha;
        bool valid = (wv >= 16.f) && (hv >= 16.f);
        float skey = valid ? sc : -INFINITY;

        int n = p * 9 + a;
        g_boxes[n * 4 + 0] = rx1;
        g_boxes[n * 4 + 1] = ry1;
        g_boxes[n * 4 + 2] = rx2;
        g_boxes[n * 4 + 3] = ry2;

        u32 b = __float_as_uint(skey);
        b = (b & 0x80000000u) ? ~b : (b | 0x80000000u);
        g_keys[n] = ((u64)(~b) << 32) | (u64)(u32)n;   // asc u64 == desc score, asc idx
    }
}

// ---------------- top-K selection: zero, histogram, scan+cut, compact ----------------
__global__ void zero_k() {
    int i = blockIdx.x * 256 + threadIdx.x;
    if (i < NBINS) g_hist[i] = 0;
    if (i < CAND_N) g_cand[i] = ~0ull;
    if (i == 0) g_cnt = 0;
}

__global__ void hist_k() {
    int i = blockIdx.x * 256 + threadIdx.x;
    if (i >= NANCH) return;
    atomicAdd(&g_hist[(int)(g_keys[i] >> 48)], 1);
}

__global__ __launch_bounds__(1024) void scan_select_k() {
    int t = threadIdx.x;
    int base = t * 64;
    int tot = 0;
#pragma unroll 8
    for (int b = 0; b < 64; ++b) tot += g_hist[base + b];
    int lane = t & 31, warp = t >> 5;
    int v = tot;
#pragma unroll
    for (int o = 1; o < 32; o <<= 1) { int n = __shfl_up_sync(~0u, v, o); if (lane >= o) v += n; }
    __shared__ int wsum[32];
    if (lane == 31) wsum[warp] = v;
    __syncthreads();
    if (warp == 0) {
        int w = wsum[lane];
#pragma unroll
        for (int o = 1; o < 32; o <<= 1) { int n = __shfl_up_sync(~0u, w, o); if (lane >= o) w += n; }
        wsum[lane] = w;
    }
    __syncthreads();
    int incl = v + (warp ? wsum[warp - 1] : 0);
    int pre = incl - tot;
    if (pre < PRE_NMS && incl >= PRE_NMS) {
        int c = pre;
        for (int b = 0; b < 64; ++b) {
            c += g_hist[base + b];
            if (c >= PRE_NMS) { g_cut = base + b; break; }
        }
    }
}

__global__ void compact_k() {
    int i = blockIdx.x * 256 + threadIdx.x;
    if (i >= NANCH) return;
    u64 k = g_keys[i];
    if ((int)(k >> 48) <= g_cut) {
        int pos = atomicAdd(&g_cnt, 1);
        if (pos < CAND_N) g_cand[pos] = k;
    }
}

// ---------------- single-block bitonic sort of 8192 candidates ----------------
__global__ __launch_bounds__(1024) void sort8k_k() {
    extern __shared__ u64 s[];
    int t = threadIdx.x;
#pragma unroll
    for (int v = 0; v < 8; ++v) s[v * 1024 + t] = g_cand[v * 1024 + t];
    __syncthreads();
    for (int k = 2; k <= CAND_N; k <<= 1) {
        for (int j = k >> 1; j > 0; j >>= 1) {
#pragma unroll
            for (int v = 0; v < 4; ++v) {
                int gid = v * 1024 + t;
                int i = ((gid & ~(j - 1)) << 1) | (gid & (j - 1));
                int p = i | j;
                bool up = ((i & k) == 0);
                u64 a = s[i], b = s[p];
                if ((a > b) == up) { s[i] = b; s[p] = a; }
            }
            __syncthreads();
        }
    }
#pragma unroll
    for (int v = 0; v < 8; ++v) g_cand[v * 1024 + t] = s[v * 1024 + t];
}

// ---------------- gather top-6000 boxes in score order ----------------
__global__ void gather_k() {
    int r = blockIdx.x * 256 + threadIdx.x;
    if (r >= PRE_NMS) return;
    u32 n = (u32)(g_cand[r] & 0xffffffffu);
    float x1 = g_boxes[n * 4 + 0];
    float y1 = g_boxes[n * 4 + 1];
    float x2 = g_boxes[n * 4 + 2];
    float y2 = g_boxes[n * 4 + 3];
    g_sx1[r] = x1; g_sy1[r] = y1; g_sx2[r] = x2; g_sy2[r] = y2;
    g_sarea[r] = (x2 - x1 + 1.f) * (y2 - y1 + 1.f);
}

// ---------------- NMS suppression bitmask, transposed [word][box] ----------------
__global__ void nms_mask_k() {
    int bi = blockIdx.y, bj = blockIdx.x;
    if (bj < bi) return;
    __shared__ float jx1[64], jy1[64], jx2[64], jy2[64], jar[64];
    int t = threadIdx.x;
    {
        int j = bj * 64 + t;
        bool v = j < PRE_NMS;
        jx1[t] = v ? g_sx1[j] : 0.f;
        jy1[t] = v ? g_sy1[j] : 0.f;
        jx2[t] = v ? g_sx2[j] : 0.f;
        jy2[t] = v ? g_sy2[j] : 0.f;
        jar[t] = v ? g_sarea[j] : 1.f;
    }
    __syncthreads();
    int i = bi * 64 + t;
    if (i >= PRE_NMS) return;
    float x1 = g_sx1[i], y1 = g_sy1[i], x2 = g_sx2[i], y2 = g_sy2[i], ar = g_sarea[i];
    u64 bits = 0;
    int jmax = PRE_NMS - bj * 64; if (jmax > 64) jmax = 64;
#pragma unroll 4
    for (int jj = 0; jj < 64; ++jj) {
        if (jj < jmax) {
            float xx1 = fmaxf(x1, jx1[jj]);
            float yy1 = fmaxf(y1, jy1[jj]);
            float xx2 = fminf(x2, jx2[jj]);
            float yy2 = fmaxf(y2, jy2[jj]);      // reference bug: max, not min
            float w = fmaxf(0.f, xx2 - xx1 + 1.f);
            float h = fmaxf(0.f, yy2 - yy1 + 1.f);
            float inter = w * h;
            float ov = inter / (ar + jar[jj] - inter);
            if (ov > 0.7f) bits |= (1ull << jj);
        }
    }
    g_maskT[(size_t)bj * PRE_NMS + i] = bits;   // coalesced in i
}

// ---------------- sequential NMS reduce + output (single block) ----------------
__global__ __launch_bounds__(128) void nms_reduce_k(float* __restrict__ out) {
    __shared__ u64 remv[NWORDS];
    __shared__ u64 diag[64];
    __shared__ int s_count;
    __shared__ int s_stop;
    __shared__ int sel[POST_NMS];
    int t = threadIdx.x;
    if (t < NWORDS) remv[t] = 0;
    if (t == 0) { s_count = 0; s_stop = 0; }
    __syncthreads();

    for (int c = 0; c < NWORDS; ++c) {
        int nvalid = PRE_NMS - c * 64; if (nvalid > 64) nvalid = 64;
        if (t < nvalid) diag[t] = g_maskT[(size_t)c * PRE_NMS + c * 64 + t];
        __syncthreads();
        if (t == 0) {
            u64 rem = remv[c];
            for (int b = 0; b < nvalid; ++b) {
                if (!((rem >> b) & 1ull)) {
                    u64 excl = (b == 63) ? 0ull : (~0ull << (b + 1));
                    rem |= diag[b] & excl;
                }
            }
            if (nvalid < 64) rem |= (~0ull << nvalid);
            remv[c] = rem;
            u64 vm = (nvalid == 64) ? ~0ull : ((1ull << nvalid) - 1ull);
            s_count += __popcll(~rem & vm);
            if (s_count >= POST_NMS || c == NWORDS - 1) s_stop = 1;
        }
        __syncthreads();
        if (s_stop) break;
        if (t > c && t < NWORDS) {
            u64 word = remv[t];
            u64 keepbits = ~remv[c];
            const u64* mrow = g_maskT + (size_t)t * PRE_NMS + c * 64;   // contiguous
#pragma unroll 16
            for (int b = 0; b < 64; ++b) {
                u64 selm = (u64)0 - ((keepbits >> b) & 1ull);
                word |= mrow[b] & selm;
            }
            remv[t] = word;
        }
        __syncthreads();
    }

    if (t == 0) {
        int cnt = 0;
        for (int c = 0; c < NWORDS && cnt < POST_NMS; ++c) {
            int nvalid = PRE_NMS - c * 64; if (nvalid > 64) nvalid = 64;
            u64 vm = (nvalid == 64) ? ~0ull : ((1ull << nvalid) - 1ull);
            u64 kept = (~remv[c]) & vm;
            while (kept && cnt < POST_NMS) {
                int b = __ffsll((long long)kept) - 1;
                kept &= kept - 1;
                sel[cnt++] = c * 64 + b;
            }
        }
        for (int c = 0; c < NWORDS && cnt < POST_NMS; ++c) {
            int nvalid = PRE_NMS - c * 64; if (nvalid > 64) nvalid = 64;
            u64 vm = (nvalid == 64) ? ~0ull : ((1ull << nvalid) - 1ull);
            u64 sup = remv[c] & vm;
            while (sup && cnt < POST_NMS) {
                int b = __ffsll((long long)sup) - 1;
                sup &= sup - 1;
                sel[cnt++] = c * 64 + b;
            }
        }
    }
    __syncthreads();
    for (int r = t; r < POST_NMS; r += 128) {
        int i = sel[r];
        float x1 = g_sx1[i], y1 = g_sy1[i], x2 = g_sx2[i], y2 = g_sy2[i];
        out[r * 4 + 0] = x1;
        out[r * 4 + 1] = y1;
        out[r * 4 + 2] = x2 - x1 + 1.f;
        out[r * 4 + 3] = y2 - y1 + 1.f;
    }
}

// ---------------- launch ----------------
extern "C" void kernel_launch(void* const* d_in, const int* in_sizes, int n_in,
                              void* d_out, int out_size) {
    const float* in_features = (const float*)d_in[0];
    const float* conv_w = (const float*)d_in[1];
    const float* conv_b = (const float*)d_in[2];
    const float* reg_w  = (const float*)d_in[3];
    const float* reg_b  = (const float*)d_in[4];
    const float* cls_w  = (const float*)d_in[5];
    const float* cls_b  = (const float*)d_in[6];
    float* out = (float*)d_out;

    static bool attr_done = false;
    if (!attr_done) {
        cudaFuncSetAttribute(sort8k_k, cudaFuncAttributeMaxDynamicSharedMemorySize, CAND_N * 8);
        attr_done = true;
    }

    const float* x7 = in_features + (size_t)7 * 512 * NPOS;   // only batch -1 is consumed

    im2col_k<<<(unsigned)(((size_t)KTOT * NPAD + 255) / 256), 256>>>(x7);
    conv_gemm_k<<<dim3(NPAD / TN, 512 / TM, SPLITK), 256>>>(conv_w);
    reduce_bias_k<<<(512 * (NPAD / 4) + 255) / 256, 256>>>(conv_b);

    head_gemm_k<<<NPAD / 32, 256>>>(reg_w, reg_b, cls_w, cls_b);
    decode_k<<<(NPOS + 255) / 256, 256>>>();

    zero_k<<<(NBINS + 255) / 256, 256>>>();
    hist_k<<<(NANCH + 255) / 256, 256>>>();
    scan_select_k<<<1, 1024>>>();
    compact_k<<<(NANCH + 255) / 256, 256>>>();
    sort8k_k<<<1, 1024, CAND_N * 8>>>();

    gather_k<<<(PRE_NMS + 255) / 256, 256>>>();
    nms_mask_k<<<dim3(NWORDS, NWORDS), 64>>>();
    nms_reduce_k<<<1, 128>>>(out);
}

// round 8
// speedup vs baseline: 1.0280x; 1.0280x over previous
#include <cuda_runtime.h>
#include <math.h>

typedef unsigned long long u64;
typedef unsigned int u32;

#define FSZ 50
#define NPOS 2500          // 50*50
#define KTOT 4608          // 512*9
#define NPAD 2560          // padded N for GEMM
#define NANCH 22500        // 2500*9
#define PRE_NMS 6000
#define NWORDS 94          // ceil(6000/64)
#define POST_NMS 300
#define NBINS 65536
#define CAND_N 8192

// GEMM config
#define TM 128
#define TN 128
#define TK 16
#define SPLITK 4
#define KS (KTOT / SPLITK)       // 1152
#define GITERS (KS / TK)         // 72
#define ASTR 132                 // padded smem row stride (floats)

// ---------------- scratch (__device__ globals; no runtime allocation) ----------------
__device__ float g_im2col[(size_t)KTOT * NPAD];          // 47.2 MB, [k][n]
__device__ float g_part[SPLITK][512][NPAD];              // 21 MB split-K partials
__device__ float g_head[(size_t)64 * NPAD];              // 0.66 MB
__device__ float g_boxes[NANCH * 4];
__device__ u64   g_keys[NANCH];
__device__ int   g_hist[NBINS];
__device__ int   g_cnt;
__device__ int   g_cut;
__device__ u64   g_cand[CAND_N];
__device__ float g_sx1[PRE_NMS], g_sy1[PRE_NMS], g_sx2[PRE_NMS], g_sy2[PRE_NMS], g_sarea[PRE_NMS];
__device__ u64   g_maskT[(size_t)NWORDS * PRE_NMS + 64]; // transposed [word][box]

// ---------------- packed fp32 helpers ----------------
__device__ __forceinline__ u64 bcast2(float x) {
    u64 r; asm("mov.b64 %0, {%1, %1};" : "=l"(r) : "f"(x)); return r;
}
__device__ __forceinline__ void ffma2(u64& acc, u64 a, u64 b) {
    asm("fma.rn.f32x2 %0, %1, %2, %0;" : "+l"(acc) : "l"(a), "l"(b));
}
__device__ __forceinline__ void unpack2(u64 v, float& lo, float& hi) {
    asm("mov.b64 {%0, %1}, %2;" : "=f"(lo), "=f"(hi) : "l"(v));
}
#define CPA(dst, src)  asm volatile("cp.async.cg.shared.global [%0], [%1], 16;" :: "r"(dst), "l"(src))
#define CPCOMMIT()     asm volatile("cp.async.commit_group;" ::: "memory")
#define CPWAIT0()      asm volatile("cp.async.wait_group 0;" ::: "memory")

// ---------------- im2col (batch 7 only) ----------------
__global__ void im2col_k(const float* __restrict__ x) {
    size_t idx = (size_t)blockIdx.x * 256 + threadIdx.x;
    if (idx >= (size_t)KTOT * NPAD) return;
    int k = (int)(idx / NPAD);
    int p = (int)(idx - (size_t)k * NPAD);
    float v = 0.f;
    if (p < NPOS) {
        int i  = k / 9;
        int r  = k - i * 9;
        int ky = r / 3;
        int kx = r - ky * 3;
        int y  = p / FSZ;
        int xw = p - y * FSZ;
        int yy = y + ky - 1;
        int xx = xw + kx - 1;
        if (yy >= 0 && yy < FSZ && xx >= 0 && xx < FSZ)
            v = x[(size_t)i * NPOS + yy * FSZ + xx];
    }
    g_im2col[idx] = v;
}

// ---------------- packed-fp32 split-K GEMM (conflict-free compute mapping) ----------------
__global__ __launch_bounds__(256) void conv_gemm_k(const float* __restrict__ W) {
    __shared__ __align__(16) float As[2][TK][ASTR];   // [k][m]
    __shared__ __align__(16) float Bs[2][TK][ASTR];   // [k][n]
    int t  = threadIdx.x;
    int m0 = blockIdx.y * TM;
    int n0 = blockIdx.x * TN;
    int z  = blockIdx.z;
    int kbase = z * KS;

    int arow = t >> 1;
    int ak   = (t & 1) * 8;
    int brow = t >> 4;
    int bn   = (t & 15) * 4;

    const float* aG = W + (size_t)(m0 + arow) * KTOT + kbase + ak;
    const float* bG = g_im2col + (size_t)(kbase + brow) * NPAD + n0 + bn;

    u32 bs0 = (u32)__cvta_generic_to_shared(&Bs[0][0][0]) + (u32)((brow * ASTR + bn) * 4);
    u32 bs1 = bs0 + (u32)(TK * ASTR * 4);

    float4 ar0 = *(const float4*)aG;
    float4 ar1 = *(const float4*)(aG + 4);
    CPA(bs0, bG);
    CPA(bs0 + 256, bG + 64);
    CPCOMMIT();

    u64 acc[4][8];
#pragma unroll
    for (int i = 0; i < 4; ++i)
#pragma unroll
        for (int j = 0; j < 8; ++j) acc[i][j] = 0ull;

    int warp = t >> 5, lane = t & 31;
    int mwarp = warp >> 1, nwarp = warp & 1;
    int lm = lane >> 3, ln = lane & 7;
    int mb = mwarp * 32 + lm * 4;
    int nb = nwarp * 64 + ln * 4;

    for (int it = 0; it < GITERS; ++it) {
        int cur = it & 1;
        CPWAIT0();
        {
            float* Ac = &As[cur][0][0];
            Ac[(ak + 0) * ASTR + arow] = ar0.x;
            Ac[(ak + 1) * ASTR + arow] = ar0.y;
            Ac[(ak + 2) * ASTR + arow] = ar0.z;
            Ac[(ak + 3) * ASTR + arow] = ar0.w;
            Ac[(ak + 4) * ASTR + arow] = ar1.x;
            Ac[(ak + 5) * ASTR + arow] = ar1.y;
            Ac[(ak + 6) * ASTR + arow] = ar1.z;
            Ac[(ak + 7) * ASTR + arow] = ar1.w;
        }
        __syncthreads();

        if (it + 1 < GITERS) {
            int nxt = cur ^ 1;
            const float* bGn = bG + (size_t)(it + 1) * TK * NPAD;
            u32 bsn = nxt ? bs1 : bs0;
            CPA(bsn, bGn);
            CPA(bsn + 256, bGn + 64);
            CPCOMMIT();
            const float* aGn = aG + (it + 1) * TK;
            ar0 = *(const float4*)aGn;
            ar1 = *(const float4*)(aGn + 4);
        }

#pragma unroll
        for (int kk = 0; kk < TK; ++kk) {
            const float* asr = &As[cur][kk][0];
            const float* bsr = &Bs[cur][kk][0];
            ulonglong2 a0 = *(const ulonglong2*)(asr + mb);
            ulonglong2 a1 = *(const ulonglong2*)(asr + mb + 16);
            float4 b0 = *(const float4*)(bsr + nb);
            float4 b1 = *(const float4*)(bsr + nb + 32);
            u64 aa[4] = {a0.x, a0.y, a1.x, a1.y};
            u64 bb[8];
            bb[0] = bcast2(b0.x); bb[1] = bcast2(b0.y);
            bb[2] = bcast2(b0.z); bb[3] = bcast2(b0.w);
            bb[4] = bcast2(b1.x); bb[5] = bcast2(b1.y);
            bb[6] = bcast2(b1.z); bb[7] = bcast2(b1.w);
#pragma unroll
            for (int mp = 0; mp < 4; ++mp)
#pragma unroll
                for (int nj = 0; nj < 8; ++nj)
                    ffma2(acc[mp][nj], aa[mp], bb[nj]);
        }
        __syncthreads();
    }

    float* outp = &g_part[z][0][0];
#pragma unroll
    for (int mp = 0; mp < 4; ++mp) {
        float lo[8], hi[8];
#pragma unroll
        for (int nj = 0; nj < 8; ++nj) unpack2(acc[mp][nj], lo[nj], hi[nj]);
        int m = m0 + mb + ((mp & 2) << 3) + ((mp & 1) << 1);
        size_t rA = (size_t)m * NPAD + n0 + nb;
        size_t rB = rA + NPAD;
        float4 v;
        v.x = lo[0]; v.y = lo[1]; v.z = lo[2]; v.w = lo[3]; *(float4*)(outp + rA)      = v;
        v.x = lo[4]; v.y = lo[5]; v.z = lo[6]; v.w = lo[7]; *(float4*)(outp + rA + 32) = v;
        v.x = hi[0]; v.y = hi[1]; v.z = hi[2]; v.w = hi[3]; *(float4*)(outp + rB)      = v;
        v.x = hi[4]; v.y = hi[5]; v.z = hi[6]; v.w = hi[7]; *(float4*)(outp + rB + 32) = v;
    }
}

// ---------------- head GEMM fused with split-K reduce + bias + leaky ----------------
// g_head[64][2560] = Whead[64][512] @ leaky(sum_z g_part[z] + conv_b)
__global__ __launch_bounds__(256) void head_gemm_k(const float* __restrict__ conv_b,
                                                   const float* __restrict__ reg_w,
                                                   const float* __restrict__ reg_b,
                                                   const float* __restrict__ cls_w,
                                                   const float* __restrict__ cls_b) {
    __shared__ __align__(16) float As[16][68];   // [k][m] 64 m
    __shared__ __align__(16) float Bs[16][36];   // [k][n] 32 n
    int t  = threadIdx.x;
    int n0 = blockIdx.x * 32;

    int arow_h = t >> 2, akk = (t & 3) * 4;   // A: 64 rows x 16 k
    int brow = t >> 3, bnl = (t & 7) * 4;     // B: 16 k x 32 n (threads < 128)

    int warp = t >> 5, lane = t & 31;
    int mwarp = warp >> 1, nwarp = warp & 1;
    int lm = lane >> 3, ln = lane & 7;
    int mb = mwarp * 16 + lm * 4;
    int nb = nwarp * 16 + ln * 2;

    float acc[4][2];
#pragma unroll
    for (int i = 0; i < 4; ++i) { acc[i][0] = 0.f; acc[i][1] = 0.f; }

    for (int it = 0; it < 32; ++it) {
        int k0 = it * 16;
        float4 av;
        if (arow_h < 36)       av = *(const float4*)(reg_w + arow_h * 512 + k0 + akk);
        else if (arow_h < 54)  av = *(const float4*)(cls_w + (arow_h - 36) * 512 + k0 + akk);
        else                   av = make_float4(0.f, 0.f, 0.f, 0.f);
        float4 fv = make_float4(0.f, 0.f, 0.f, 0.f);
        if (t < 128) {
            size_t off = (size_t)(k0 + brow) * NPAD + n0 + bnl;
            float4 a = *(const float4*)(&g_part[0][0][0] + off);
            float4 b = *(const float4*)(&g_part[1][0][0] + off);
            float4 c = *(const float4*)(&g_part[2][0][0] + off);
            float4 d = *(const float4*)(&g_part[3][0][0] + off);
            float bv = conv_b[k0 + brow];
            float v;
            v = a.x + b.x + c.x + d.x + bv; fv.x = (v >= 0.f) ? v : 0.01f * v;
            v = a.y + b.y + c.y + d.y + bv; fv.y = (v >= 0.f) ? v : 0.01f * v;
            v = a.z + b.z + c.z + d.z + bv; fv.z = (v >= 0.f) ? v : 0.01f * v;
            v = a.w + b.w + c.w + d.w + bv; fv.w = (v >= 0.f) ? v : 0.01f * v;
        }
        __syncthreads();
        As[akk + 0][arow_h] = av.x;
        As[akk + 1][arow_h] = av.y;
        As[akk + 2][arow_h] = av.z;
        As[akk + 3][arow_h] = av.w;
        if (t < 128) *(float4*)&Bs[brow][bnl] = fv;
        __syncthreads();
#pragma unroll
        for (int kk = 0; kk < 16; ++kk) {
            float4 a4 = *(const float4*)(&As[kk][mb]);
            float2 b2 = *(const float2*)(&Bs[kk][nb]);
            float am[4] = {a4.x, a4.y, a4.z, a4.w};
#pragma unroll
            for (int mi = 0; mi < 4; ++mi) {
                acc[mi][0] = fmaf(am[mi], b2.x, acc[mi][0]);
                acc[mi][1] = fmaf(am[mi], b2.y, acc[mi][1]);
            }
        }
    }

#pragma unroll
    for (int mi = 0; mi < 4; ++mi) {
        int m = mb + mi;
        float bv = 0.f;
        if (m < 36) bv = reg_b[m];
        else if (m < 54) bv = cls_b[m - 36];
        float2 o;
        o.x = acc[mi][0] + bv;
        o.y = acc[mi][1] + bv;
        *(float2*)(g_head + (size_t)m * NPAD + n0 + nb) = o;
    }
}

// ---------------- init: hist zero + candidate padding + counter ----------------
__global__ void zero_k() {
    int i = blockIdx.x * 256 + threadIdx.x;
    if (i < NBINS) g_hist[i] = 0;
    if (i < CAND_N) g_cand[i] = ~0ull;
    if (i == 0) g_cnt = 0;
}

// ---------------- decode: softmax + box decode + sort keys + histogram (fused) ----------------
__global__ void decode_k() {
    int p = blockIdx.x * 256 + threadIdx.x;
    if (p >= NPOS) return;
    float ho[54];
#pragma unroll
    for (int j = 0; j < 54; ++j) ho[j] = g_head[(size_t)j * NPAD + p];

    int irow = p / FSZ, jcol = p - irow * FSZ;
    float cx = 16.f * (float)irow + 8.f;
    float cy = 16.f * (float)jcol + 8.f;

#pragma unroll
    for (int a = 0; a < 9; ++a) {
        int r = a / 3, s = a % 3;
        float ssv = 16.0f * ((s == 0) ? 8.f : (s == 1) ? 16.f : 32.f);
        float rsv = (r == 0) ? 0.5f : (r == 1) ? 1.f : 2.f;
        float ha = ssv * sqrtf(rsv);
        float wa = ssv * sqrtf(1.0f / rsv);
        float x1a = cx - wa * 0.5f;
        float y1a = cy - ha * 0.5f;

        float pr0 = ho[a * 4 + 0], pr1 = ho[a * 4 + 1], pr2 = ho[a * 4 + 2], pr3 = ho[a * 4 + 3];
        float c0 = ho[36 + a * 2 + 0], c1 = ho[36 + a * 2 + 1];
        float mx = fmaxf(c0, c1);
        float e0 = expf(c0 - mx), e1 = expf(c1 - mx);
        float sc = e1 / (e0 + e1);

        const float hi = 799.f;
        float t0 = pr0 + x1a, t1 = pr1 + y1a;
        float rx1 = fminf(fmaxf(t0, 0.f), hi);
        float ry1 = fminf(fmaxf(t1, 0.f), hi);
        float rx2 = fminf(fmaxf((t0 + pr2) + wa, 0.f), hi);
        float ry2 = fminf(fmaxf((t1 + pr3) + ha, 0.f), hi);
        float wv = pr2 + wa, hv = pr3 + ha;
        bool valid = (wv >= 16.f) && (hv >= 16.f);
        float skey = valid ? sc : -INFINITY;

        int n = p * 9 + a;
        g_boxes[n * 4 + 0] = rx1;
        g_boxes[n * 4 + 1] = ry1;
        g_boxes[n * 4 + 2] = rx2;
        g_boxes[n * 4 + 3] = ry2;

        u32 b = __float_as_uint(skey);
        b = (b & 0x80000000u) ? ~b : (b | 0x80000000u);
        u64 key = ((u64)(~b) << 32) | (u64)(u32)n;   // asc u64 == desc score, asc idx
        g_keys[n] = key;
        atomicAdd(&g_hist[(int)(key >> 48)], 1);
    }
}

// ---------------- scan histogram, find cutoff bin ----------------
__global__ __launch_bounds__(1024) void scan_select_k() {
    int t = threadIdx.x;
    int base = t * 64;
    int tot = 0;
#pragma unroll 8
    for (int b = 0; b < 64; ++b) tot += g_hist[base + b];
    int lane = t & 31, warp = t >> 5;
    int v = tot;
#pragma unroll
    for (int o = 1; o < 32; o <<= 1) { int n = __shfl_up_sync(~0u, v, o); if (lane >= o) v += n; }
    __shared__ int wsum[32];
    if (lane == 31) wsum[warp] = v;
    __syncthreads();
    if (warp == 0) {
        int w = wsum[lane];
#pragma unroll
        for (int o = 1; o < 32; o <<= 1) { int n = __shfl_up_sync(~0u, w, o); if (lane >= o) w += n; }
        wsum[lane] = w;
    }
    __syncthreads();
    int incl = v + (warp ? wsum[warp - 1] : 0);
    int pre = incl - tot;
    if (pre < PRE_NMS && incl >= PRE_NMS) {
        int c = pre;
        for (int b = 0; b < 64; ++b) {
            c += g_hist[base + b];
            if (c >= PRE_NMS) { g_cut = base + b; break; }
        }
    }
}

__global__ void compact_k() {
    int i = blockIdx.x * 256 + threadIdx.x;
    if (i >= NANCH) return;
    u64 k = g_keys[i];
    if ((int)(k >> 48) <= g_cut) {
        int pos = atomicAdd(&g_cnt, 1);
        if (pos < CAND_N) g_cand[pos] = k;
    }
}

// ---------------- multi-block bitonic sort of 8192 candidates ----------------
__global__ __launch_bounds__(1024) void sort8_p1() {
    __shared__ u64 s[2048];
    int t = threadIdx.x;
    int base = blockIdx.x * 2048;
    s[t] = g_cand[base + t];
    s[t + 1024] = g_cand[base + t + 1024];
    __syncthreads();
    for (int k = 2; k <= 2048; k <<= 1) {
        for (int j = k >> 1; j > 0; j >>= 1) {
            int li = ((t & ~(j - 1)) << 1) | (t & (j - 1));
            int pr = li | j;
            bool up = (((base + li) & k) == 0);
            u64 a = s[li], b = s[pr];
            if ((a > b) == up) { s[li] = b; s[pr] = a; }
            __syncthreads();
        }
    }
    g_cand[base + t] = s[t];
    g_cand[base + t + 1024] = s[t + 1024];
}

__global__ __launch_bounds__(1024) void sort8_g(int j, int k) {
    int t = blockIdx.x * 1024 + threadIdx.x;   // CAND_N/2 threads
    int i = ((t & ~(j - 1)) << 1) | (t & (j - 1));
    int pr = i | j;
    bool up = ((i & k) == 0);
    u64 a = g_cand[i], b = g_cand[pr];
    if ((a > b) == up) { g_cand[i] = b; g_cand[pr] = a; }
}

__global__ __launch_bounds__(1024) void sort8_l(int k) {
    __shared__ u64 s[2048];
    int t = threadIdx.x;
    int base = blockIdx.x * 2048;
    s[t] = g_cand[base + t];
    s[t + 1024] = g_cand[base + t + 1024];
    __syncthreads();
    for (int j = 1024; j > 0; j >>= 1) {
        int li = ((t & ~(j - 1)) << 1) | (t & (j - 1));
        int pr = li | j;
        bool up = (((base + li) & k) == 0);
        u64 a = s[li], b = s[pr];
        if ((a > b) == up) { s[li] = b; s[pr] = a; }
        __syncthreads();
    }
    g_cand[base + t] = s[t];
    g_cand[base + t + 1024] = s[t + 1024];
}

// ---------------- gather top-6000 boxes in score order ----------------
__global__ void gather_k() {
    int r = blockIdx.x * 256 + threadIdx.x;
    if (r >= PRE_NMS) return;
    u32 n = (u32)(g_cand[r] & 0xffffffffu);
    float x1 = g_boxes[n * 4 + 0];
    float y1 = g_boxes[n * 4 + 1];
    float x2 = g_boxes[n * 4 + 2];
    float y2 = g_boxes[n * 4 + 3];
    g_sx1[r] = x1; g_sy1[r] = y1; g_sx2[r] = x2; g_sy2[r] = y2;
    g_sarea[r] = (x2 - x1 + 1.f) * (y2 - y1 + 1.f);
}

// ---------------- NMS suppression bitmask, transposed [word][box] ----------------
__global__ void nms_mask_k() {
    int bi = blockIdx.y, bj = blockIdx.x;
    if (bj < bi) return;
    __shared__ float jx1[64], jy1[64], jx2[64], jy2[64], jar[64];
    int t = threadIdx.x;
    {
        int j = bj * 64 + t;
        bool v = j < PRE_NMS;
        jx1[t] = v ? g_sx1[j] : 0.f;
        jy1[t] = v ? g_sy1[j] : 0.f;
        jx2[t] = v ? g_sx2[j] : 0.f;
        jy2[t] = v ? g_sy2[j] : 0.f;
        jar[t] = v ? g_sarea[j] : 1.f;
    }
    __syncthreads();
    int i = bi * 64 + t;
    if (i >= PRE_NMS) return;
    float x1 = g_sx1[i], y1 = g_sy1[i], x2 = g_sx2[i], y2 = g_sy2[i], ar = g_sarea[i];
    u64 bits = 0;
    int jmax = PRE_NMS - bj * 64; if (jmax > 64) jmax = 64;
#pragma unroll 4
    for (int jj = 0; jj < 64; ++jj) {
        if (jj < jmax) {
            float xx1 = fmaxf(x1, jx1[jj]);
            float yy1 = fmaxf(y1, jy1[jj]);
            float xx2 = fminf(x2, jx2[jj]);
            float yy2 = fmaxf(y2, jy2[jj]);      // reference bug: max, not min
            float w = fmaxf(0.f, xx2 - xx1 + 1.f);
            float h = fmaxf(0.f, yy2 - yy1 + 1.f);
            float inter = w * h;
            float ov = inter / (ar + jar[jj] - inter);
            if (ov > 0.7f) bits |= (1ull << jj);
        }
    }
    g_maskT[(size_t)bj * PRE_NMS + i] = bits;   // coalesced in i
}

// ---------------- sequential NMS reduce + output (single block) ----------------
__global__ __launch_bounds__(128) void nms_reduce_k(float* __restrict__ out) {
    __shared__ u64 remv[NWORDS];
    __shared__ u64 diag[64];
    __shared__ int s_count;
    __shared__ int s_stop;
    __shared__ int sel[POST_NMS];
    int t = threadIdx.x;
    if (t < NWORDS) remv[t] = 0;
    if (t == 0) { s_count = 0; s_stop = 0; }
    __syncthreads();

    for (int c = 0; c < NWORDS; ++c) {
        int nvalid = PRE_NMS - c * 64; if (nvalid > 64) nvalid = 64;
        if (t < nvalid) diag[t] = g_maskT[(size_t)c * PRE_NMS + c * 64 + t];
        __syncthreads();
        if (t == 0) {
            u64 rem = remv[c];
            for (int b = 0; b < nvalid; ++b) {
                if (!((rem >> b) & 1ull)) {
                    u64 excl = (b == 63) ? 0ull : (~0ull << (b + 1));
                    rem |= diag[b] & excl;
                }
            }
            if (nvalid < 64) rem |= (~0ull << nvalid);
            remv[c] = rem;
            u64 vm = (nvalid == 64) ? ~0ull : ((1ull << nvalid) - 1ull);
            s_count += __popcll(~rem & vm);
            if (s_count >= POST_NMS || c == NWORDS - 1) s_stop = 1;
        }
        __syncthreads();
        if (s_stop) break;
        if (t > c && t < NWORDS) {
            u64 word = remv[t];
            u64 keepbits = ~remv[c];
            const u64* mrow = g_maskT + (size_t)t * PRE_NMS + c * 64;   // contiguous
#pragma unroll 16
            for (int b = 0; b < 64; ++b) {
                u64 selm = (u64)0 - ((keepbits >> b) & 1ull);
                word |= mrow[b] & selm;
            }
            remv[t] = word;
        }
        __syncthreads();
    }

    if (t == 0) {
        int cnt = 0;
        for (int c = 0; c < NWORDS && cnt < POST_NMS; ++c) {
            int nvalid = PRE_NMS - c * 64; if (nvalid > 64) nvalid = 64;
            u64 vm = (nvalid == 64) ? ~0ull : ((1ull << nvalid) - 1ull);
            u64 kept = (~remv[c]) & vm;
            while (kept && cnt < POST_NMS) {
                int b = __ffsll((long long)kept) - 1;
                kept &= kept - 1;
                sel[cnt++] = c * 64 + b;
            }
        }
        for (int c = 0; c < NWORDS && cnt < POST_NMS; ++c) {
            int nvalid = PRE_NMS - c * 64; if (nvalid > 64) nvalid = 64;
            u64 vm = (nvalid == 64) ? ~0ull : ((1ull << nvalid) - 1ull);
            u64 sup = remv[c] & vm;
            while (sup && cnt < POST_NMS) {
                int b = __ffsll((long long)sup) - 1;
                sup &= sup - 1;
                sel[cnt++] = c * 64 + b;
            }
        }
    }
    __syncthreads();
    for (int r = t; r < POST_NMS; r += 128) {
        int i = sel[r];
        float x1 = g_sx1[i], y1 = g_sy1[i], x2 = g_sx2[i], y2 = g_sy2[i];
        out[r * 4 + 0] = x1;
        out[r * 4 + 1] = y1;
        out[r * 4 + 2] = x2 - x1 + 1.f;
        out[r * 4 + 3] = y2 - y1 + 1.f;
    }
}

// ---------------- launch ----------------
extern "C" void kernel_launch(void* const* d_in, const int* in_sizes, int n_in,
                              void* d_out, int out_size) {
    const float* in_features = (const float*)d_in[0];
    const float* conv_w = (const float*)d_in[1];
    const float* conv_b = (const float*)d_in[2];
    const float* reg_w  = (const float*)d_in[3];
    const float* reg_b  = (const float*)d_in[4];
    const float* cls_w  = (const float*)d_in[5];
    const float* cls_b  = (const float*)d_in[6];
    float* out = (float*)d_out;

    const float* x7 = in_features + (size_t)7 * 512 * NPOS;   // only batch -1 is consumed

    im2col_k<<<(unsigned)(((size_t)KTOT * NPAD + 255) / 256), 256>>>(x7);
    conv_gemm_k<<<dim3(NPAD / TN, 512 / TM, SPLITK), 256>>>(conv_w);

    zero_k<<<(NBINS + 255) / 256, 256>>>();
    head_gemm_k<<<NPAD / 32, 256>>>(conv_b, reg_w, reg_b, cls_w, cls_b);
    decode_k<<<(NPOS + 255) / 256, 256>>>();

    scan_select_k<<<1, 1024>>>();
    compact_k<<<(NANCH + 255) / 256, 256>>>();

    sort8_p1<<<CAND_N / 2048, 1024>>>();
    sort8_g<<<CAND_N / 2048, 1024>>>(2048, 4096);
    sort8_l<<<CAND_N / 2048, 1024>>>(4096);
    sort8_g<<<CAND_N / 2048, 1024>>>(4096, 8192);
    sort8_g<<<CAND_N / 2048, 1024>>>(2048, 8192);
    sort8_l<<<CAND_N / 2048, 1024>>>(8192);

    gather_k<<<(PRE_NMS + 255) / 256, 256>>>();
    nms_mask_k<<<dim3(NWORDS, NWORDS), 64>>>();
    nms_reduce_k<<<1, 128>>>(out);
}